// round 9
// baseline (speedup 1.0000x reference)
#include <cuda_runtime.h>
#include <cstdint>

#define BB 32
#define TT 4096
#define HH 256
#define TILE_ROWS 32
#define TILE_BYTES (TILE_ROWS * HH * 4)     // 32 KB per tile
#define CHUNKS (TT / TILE_ROWS)             // 128 tiles per batch
#define NTILES (BB * CHUNKS)                // 4096 tiles total
#define NTHREADS 256
#define NWARPS 8
#define ROWS_PER_WARP (TILE_ROWS / NWARPS)  // 4
#define GRID 444                            // 148 SMs x 3 CTAs = one wave

#define ALPHA 0.1f
#define LOG2_09 (-0.15200309344504997f)     // log2(0.9)
#define MASK_PENALTY 1000000.0f

__device__ float g_partial[NTILES];
__device__ unsigned int g_work = 0;
__device__ unsigned int g_done = 0;

__device__ __forceinline__ uint32_t s2u(const void* p) {
    uint32_t a;
    asm("{ .reg .u64 t; cvta.to.shared.u64 t, %1; cvt.u32.u64 %0, t; }"
        : "=r"(a) : "l"(p));
    return a;
}

__device__ __forceinline__ void mbar_init(uint32_t mbar, uint32_t cnt) {
    asm volatile("mbarrier.init.shared.b64 [%0], %1;" :: "r"(mbar), "r"(cnt) : "memory");
}
__device__ __forceinline__ void mbar_expect_tx(uint32_t mbar, uint32_t bytes) {
    asm volatile("mbarrier.arrive.expect_tx.shared.b64 _, [%0], %1;"
                 :: "r"(mbar), "r"(bytes) : "memory");
}
__device__ __forceinline__ void mbar_wait(uint32_t mbar, uint32_t phase) {
    asm volatile(
        "{\n\t"
        ".reg .pred P;\n\t"
        "L_%=:\n\t"
        "mbarrier.try_wait.parity.acquire.cta.shared::cta.b64 P, [%0], %1, 0x989680;\n\t"
        "@P bra D_%=;\n\t"
        "bra L_%=;\n\t"
        "D_%=:\n\t"
        "}"
        :: "r"(mbar), "r"(phase) : "memory");
}
__device__ __forceinline__ void bulk_copy(uint32_t dst_smem, const void* src,
                                          uint32_t bytes, uint32_t mbar) {
    asm volatile(
        "cp.async.bulk.shared::cta.global.mbarrier::complete_tx::bytes [%0], [%1], %2, [%3];"
        :: "r"(dst_smem), "l"(src), "r"(bytes), "r"(mbar) : "memory");
}

__global__ __launch_bounds__(NTHREADS)
void pool_bulk(const float* __restrict__ x,
               const int*   __restrict__ mask,
               const float* __restrict__ weight_ema,
               const float* __restrict__ weight_mean,
               const float* __restrict__ W,
               const float* __restrict__ bias,
               float*       __restrict__ out)
{
    extern __shared__ float4 smem[];                 // 2 stages x 32 KB
    __shared__ __align__(8) unsigned long long mbar_storage[2];
    __shared__ float s_warp_acc[NWARPS];
    __shared__ int   s_tile;
    __shared__ bool  s_is_last;

    const int tid  = threadIdx.x;
    const int wid  = tid >> 5;
    const int lane = tid & 31;

    const uint32_t mb0 = s2u(&mbar_storage[0]);
    const uint32_t mb1 = s2u(&mbar_storage[1]);
    const uint32_t smem_base = s2u(smem);

    if (tid == 0) { mbar_init(mb0, 1); mbar_init(mb1, 1); }
    __syncthreads();

    // Per-lane W slices
    const float4* W4 = reinterpret_cast<const float4*>(W);
    const float4 wa = __ldg(W4 + lane);
    const float4 wb = __ldg(W4 + 32 + lane);

    float wsum = wa.x + wa.y + wa.z + wa.w + wb.x + wb.y + wb.z + wb.w;
    #pragma unroll
    for (int off = 16; off > 0; off >>= 1)
        wsum += __shfl_xor_sync(0xffffffffu, wsum, off);

    const float we        = __ldg(weight_ema);
    const float wm_over_T = __ldg(weight_mean) * (1.0f / (float)TT);
    const float cs        = we * ALPHA;
    const float penw      = MASK_PENALTY * wsum;

    int pending[2];
    int full_phase[2] = {0, 0};

    // --- prologue: fetch + issue two tiles ---
    #pragma unroll
    for (int k = 0; k < 2; k++) {
        __syncthreads();
        if (tid == 0) s_tile = (int)atomicAdd(&g_work, 1u);
        __syncthreads();
        const int t = s_tile;
        pending[k] = t;
        if (tid == 0 && t < NTILES) {
            const uint32_t mb = k ? mb1 : mb0;
            mbar_expect_tx(mb, TILE_BYTES);
            bulk_copy(smem_base + k * TILE_BYTES,
                      x + (size_t)t * (TILE_BYTES / 4), TILE_BYTES, mb);
        }
    }

    // --- main loop ---
    int it = 0;
    while (true) {
        const int buf  = it & 1;
        const int tile = pending[buf];
        if (tile >= NTILES) break;

        const uint32_t mb = buf ? mb1 : mb0;
        mbar_wait(mb, (uint32_t)full_phase[buf]);
        full_phase[buf] ^= 1;

        const int b  = tile / CHUNKS;
        const int t0 = (tile % CHUNKS) * TILE_ROWS;

        // mask bits for this warp's 4 rows (rows r = wid + 8*j)
        int mv = (lane < ROWS_PER_WARP)
               ? __ldg(mask + b * TT + t0 + wid + NWARPS * lane) : 1;
        const unsigned penbits =
            __ballot_sync(0xffffffffu, (lane < ROWS_PER_WARP) && (mv == 0));

        const float4* bufp = smem + buf * (TILE_BYTES / 16);

        float acc = 0.0f, pen_sum = 0.0f;
        #pragma unroll
        for (int j = 0; j < ROWS_PER_WARP; j++) {
            const int r = wid + NWARPS * j;
            float4 a  = bufp[r * (HH / 4) + lane];
            float4 c2 = bufp[r * (HH / 4) + 32 + lane];

            const int t = t0 + r;
            float wt = exp2f((float)(TT - 1 - t) * LOG2_09);
            float c  = fmaf(cs, wt, wm_over_T);
            if (t == 0) c = fmaf(we, wt, wm_over_T);   // row 0 lacks alpha

            float p0 = a.x * wa.x;
            float p1 = a.y * wa.y;
            p0 = fmaf(a.z,  wa.z, p0);
            p1 = fmaf(a.w,  wa.w, p1);
            p0 = fmaf(c2.x, wb.x, p0);
            p1 = fmaf(c2.y, wb.y, p1);
            p0 = fmaf(c2.z, wb.z, p0);
            p1 = fmaf(c2.w, wb.w, p1);

            acc = fmaf(c, p0 + p1, acc);
            if ((penbits >> j) & 1u) pen_sum += c;
        }

        #pragma unroll
        for (int off = 16; off > 0; off >>= 1)
            acc += __shfl_xor_sync(0xffffffffu, acc, off);

        if (lane == 0) s_warp_acc[wid] = acc - pen_sum * penw;
        __syncthreads();                       // all warps done reading buf

        if (tid == 0) {
            float v = 0.0f;
            #pragma unroll
            for (int w = 0; w < NWARPS; w++) v += s_warp_acc[w];  // fixed order
            g_partial[tile] = v;
            s_tile = (int)atomicAdd(&g_work, 1u);
        }
        __syncthreads();
        const int tnew = s_tile;
        pending[buf] = tnew;
        if (tid == 0 && tnew < NTILES) {
            mbar_expect_tx(mb, TILE_BYTES);
            bulk_copy(smem_base + buf * TILE_BYTES,
                      x + (size_t)tnew * (TILE_BYTES / 4), TILE_BYTES, mb);
        }
        it++;
    }

    // --- completion + final fold ---
    if (tid == 0) {
        __threadfence();
        unsigned ticket = atomicAdd(&g_done, 1u);
        s_is_last = (ticket == (unsigned)(GRID - 1));
    }
    __syncthreads();

    if (s_is_last) {
        const float bv = __ldg(bias);
        // 8 warps x 4 batches; each batch folds 128 tile partials.
        #pragma unroll
        for (int k = 0; k < BB / NWARPS; k++) {
            const int bb = wid * (BB / NWARPS) + k;
            float v = 0.0f;
            #pragma unroll
            for (int m = 0; m < CHUNKS / 32; m++)
                v += __ldcg(&g_partial[bb * CHUNKS + m * 32 + lane]);
            #pragma unroll
            for (int off = 16; off > 0; off >>= 1)
                v += __shfl_xor_sync(0xffffffffu, v, off);
            if (lane == 0) out[bb] = v + bv;
        }
        if (tid == 0) { g_work = 0; g_done = 0; }   // reset for next replay
    }
}

extern "C" void kernel_launch(void* const* d_in, const int* in_sizes, int n_in,
                              void* d_out, int out_size)
{
    const float* x    = (const float*)d_in[0];
    const int*   mask = (const int*)d_in[1];
    const float* we   = (const float*)d_in[2];
    const float* wm   = (const float*)d_in[3];
    const float* W    = (const float*)d_in[4];
    const float* bias = (const float*)d_in[5];
    float* out = (float*)d_out;

    static bool attr_set = false;
    if (!attr_set) {
        cudaFuncSetAttribute(pool_bulk,
                             cudaFuncAttributeMaxDynamicSharedMemorySize,
                             2 * TILE_BYTES);
        attr_set = true;
    }
    pool_bulk<<<GRID, NTHREADS, 2 * TILE_BYTES>>>(x, mask, we, wm, W, bias, out);
}